// round 17
// baseline (speedup 1.0000x reference)
#include <cuda_runtime.h>
#include <cstdint>

#define Cn 16
#define Hn 512
#define Wn 512
#define HWn (Hn*Wn)
#define NSTEPS 8
#define GRIDX 304          // 2 CTAs per SM
#define NTHREADS 256
#define NTILES 2048
#define RSU 132            // rows segment stride (uint2 units); px p at index 2+p

// ---- smem word offsets ----
#define OFF_W1  0                         // 10240 words (uint4[5kc][128n][4q] interleaved h/l)
#define OFF_W2  10240                     // 2048 words (uint4[8kc][16n][4q])
#define OFF_B1  12288
#define OFF_B2  12416
#define OFF_R   12432                     // 2 x 24 segs x 132 uint2
#define RBUFSZ_U2 (24*RSU)                // 3168 uint2 = 6336 words
#define SMEM_WORDS (OFF_R + 2*2*RBUFSZ_U2/2)  // 12432 + 12672 = 25104... keep explicit:
#undef SMEM_WORDS
#define SMEM_WORDS (OFF_R + 4*RBUFSZ_U2/1)    // words: 2 bufs x 3168 uint2 x 2 words = 25104? compute: 12432+2*6336=25104
#undef SMEM_WORDS
#define SMEM_WORDS 25104                  // -> 100416 B (x2 CTA = 200.8KB <= 227KB)

__device__ float    g_bufF[Cn*HWn];       // dummy f32 dst for warm steps
__device__ uint2    g_PA[8*HWn];          // interleaved (hi, lo) packed channel-pair planes
__device__ uint2    g_PB[8*HWn];
__device__ uint4    g_w1[2560];           // (bh.x, bh.y, bl.x, bl.y)
__device__ uint4    g_w2[512];

__device__ __forceinline__ uint32_t packbf(float hi, float lo) {
    uint32_t d;
    asm("cvt.rn.bf16x2.f32 %0, %1, %2;" : "=r"(d) : "f"(hi), "f"(lo));
    return d;
}
__device__ __forceinline__ float hi_f(uint32_t p) { return __uint_as_float(p & 0xFFFF0000u); }
__device__ __forceinline__ float lo_f(uint32_t p) { return __uint_as_float(p << 16); }

__device__ __forceinline__ uint32_t smem_u32(const void* p) {
    uint32_t a;
    asm("{ .reg .u64 t; cvta.to.shared.u64 t, %1; cvt.u32.u64 %0, t; }" : "=r"(a) : "l"(p));
    return a;
}
__device__ __forceinline__ void cpa8(uint32_t d, const void* g) {
    asm volatile("cp.async.ca.shared.global [%0], [%1], 8;" :: "r"(d), "l"(g));
}
__device__ __forceinline__ void cpa16(uint32_t d, const void* g) {
    asm volatile("cp.async.cg.shared.global [%0], [%1], 16;" :: "r"(d), "l"(g));
}
#define CP_COMMIT() asm volatile("cp.async.commit_group;" ::: "memory")
#define CP_WAIT0()  asm volatile("cp.async.wait_group 0;" ::: "memory")

__device__ __forceinline__ void mma16(float* d,
    uint32_t a0, uint32_t a1, uint32_t a2, uint32_t a3,
    uint32_t b0, uint32_t b1)
{
    asm volatile(
        "mma.sync.aligned.m16n8k16.row.col.f32.bf16.bf16.f32 "
        "{%0,%1,%2,%3}, {%4,%5,%6,%7}, {%8,%9}, {%0,%1,%2,%3};"
        : "+f"(d[0]), "+f"(d[1]), "+f"(d[2]), "+f"(d[3])
        : "r"(a0), "r"(a1), "r"(a2), "r"(a3), "r"(b0), "r"(b1));
}

// ---- weight bf16-split + packed-pair relayout (interleaved hi/lo) ----
__global__ void w_setup(const float* __restrict__ W1, const float* __restrict__ W2) {
    int t = threadIdx.x;
    for (int i = t; i < 2560; i += 256) {        // W1[k][n], k<80
        int kc = i >> 9, rem = i & 511;
        int n = rem >> 2, q = rem & 3;
        int k0 = kc*16 + 2*q;
        float v0 = W1[(k0  )*128 + n], v1 = W1[(k0+1)*128 + n];
        float v8 = W1[(k0+8)*128 + n], v9 = W1[(k0+9)*128 + n];
        uint32_t h0 = packbf(v1, v0), h1 = packbf(v9, v8);
        g_w1[i] = make_uint4(h0, h1,
                             packbf(v1 - hi_f(h0), v0 - lo_f(h0)),
                             packbf(v9 - hi_f(h1), v8 - lo_f(h1)));
    }
    for (int i = t; i < 512; i += 256) {         // W2[k][n], k<128
        int kc = i >> 6, rem = i & 63;
        int n = rem >> 2, q = rem & 3;
        int k0 = kc*16 + 2*q;
        float v0 = W2[(k0  )*16 + n], v1 = W2[(k0+1)*16 + n];
        float v8 = W2[(k0+8)*16 + n], v9 = W2[(k0+9)*16 + n];
        uint32_t h0 = packbf(v1, v0), h1 = packbf(v9, v8);
        g_w2[i] = make_uint4(h0, h1,
                             packbf(v1 - hi_f(h0), v0 - lo_f(h0)),
                             packbf(v9 - hi_f(h1), v8 - lo_f(h1)));
    }
}

// ---- one-time: build interleaved packed channel-pair planes ----
__global__ void pack_state(const float* __restrict__ s, uint2* __restrict__ P) {
    int i = blockIdx.x*256 + threadIdx.x;
    int pc = i >> 18, pix = i & (HWn-1);
    float v0 = s[(2*pc  )*HWn + pix];
    float v1 = s[(2*pc+1)*HWn + pix];
    uint32_t ph = packbf(v1, v0);
    P[i] = make_uint2(ph, packbf(v1 - hi_f(ph), v0 - lo_f(ph)));
}

// stage one tile: 24 interleaved segs (8 pc x 3 rows); interior 16B, 8B edges
__device__ __forceinline__ void stage_tile(const uint2* __restrict__ P,
                                           uint32_t sbase, int rbu2,
                                           int y, int x0, int w, int lane)
{
    const int ym = (y == 0)    ? 0 : (y - 1);
    const int yp = (y == Hn-1) ? 0 : (y + 1);
    #pragma unroll 1
    for (int s = w; s < 24; s += 8) {
        uint32_t dbase = sbase + (uint32_t)(rbu2 + s*RSU) * 8u;
        int pc = s / 3, ri = s - pc*3;
        int gy = (ri == 0) ? ym : ((ri == 1) ? y : yp);
        const uint2* gsrc = P + pc*HWn + gy*Wn;
        // interior 128 px = 64 cpa16 (2 px each); px p at uint2-index 2+p
        #pragma unroll
        for (int j0 = 0; j0 < 64; j0 += 32)
            cpa16(dbase + 16u*(1 + j0 + lane), gsrc + x0 + 2*(j0 + lane));
        // halo edges: lane0 -> j=0 (index 1), lane1 -> j=129 (index 130)
        if (lane < 2) {
            int j  = lane ? 129 : 0;
            int gx = x0 - 1 + j;
            gx = (gx < 0)   ? 0 : gx;   // clamp low edge
            gx = (gx >= Wn) ? 0 : gx;   // wrap high edge
            cpa8(dbase + 8u*(1 + j), gsrc + gx);
        }
    }
}

__global__ void __launch_bounds__(NTHREADS, 2)
slime_step_mma(const uint2* __restrict__ srcP, uint2* __restrict__ dstP,
               float* __restrict__ dstF, int writeF32,
               const float* __restrict__ gb1, const float* __restrict__ gb2)
{
    extern __shared__ float sm[];
    const uint32_t sbase = smem_u32(sm);
    const int tid = threadIdx.x;
    const int w = tid >> 5, lane = tid & 31;
    const int gr = lane >> 2, q = lane & 3;

    // ---- prologue: packed weights + biases to SMEM ----
    {
        uint4* d = (uint4*)(sm + OFF_W1);
        const uint4* s = (const uint4*)g_w1;
        #pragma unroll
        for (int i = 0; i < 10; i++) d[i*NTHREADS + tid] = s[i*NTHREADS + tid];
        uint4* d2 = (uint4*)(sm + OFF_W2);
        const uint4* s2 = (const uint4*)g_w2;
        #pragma unroll
        for (int i = 0; i < 2; i++) d2[i*NTHREADS + tid] = s2[i*NTHREADS + tid];
        if (tid < 128) sm[OFF_B1 + tid] = gb1[tid];
        if (tid < 16)  sm[OFF_B2 + tid] = gb2[tid];
    }

    // ---- tile-invariant A offsets (uint2 units): dir kc -> (ri,dx) ----
    int foH[10];
    {
        const int riA[5] = {1, 0, 2, 1, 1};
        const int dxA[5] = {0, 0, 0, -1, 1};
        #pragma unroll
        for (int kc = 0; kc < 5; kc++)
            #pragma unroll
            for (int p = 0; p < 2; p++)
                foH[kc*2+p] = ((q + 4*p)*3 + riA[kc])*RSU + 2 + dxA[kc];
    }

    const int R2 = w * 16;                 // warp owns 16 px

    const uint4* W1v = (const uint4*)(sm + OFF_W1);
    const uint4* W2v = (const uint4*)(sm + OFF_W2);
    const float* b1s = sm + OFF_B1;
    const float* b2s = sm + OFF_B2;

    const int t0 = blockIdx.x;
    if (t0 < NTILES)
        stage_tile(srcP, sbase, OFF_R*0 + 12432*0 + 0 + /*base*/0 + 0 + 0 + 0 + 0 + 0 + 0 + 0 + 0 + 0 + 0 + 0 + 0 + 0 + 0 + 0 + (12432/2)*0 + 6216*0 + 0 + 6216, t0 >> 2, (t0 & 3) << 7, w, lane);
    CP_COMMIT();
    CP_WAIT0();
    __syncthreads();

    int pb = 0;
    #pragma unroll 1
    for (int t = t0; t < NTILES; t += GRIDX) {
        const int y = t >> 2, x0 = (t & 3) << 7;
        const int rbu2  = 6216 + (pb ? RBUFSZ_U2 : 0);          // OFF_R/2 = 6216 uint2
        const int rbu2n = 6216 + (pb ? 0 : RBUFSZ_U2);
        const uint2* ruu = ((const uint2*)sm) + rbu2;

        const int tn = t + GRIDX;
        if (tn < NTILES)
            stage_tile(srcP, sbase, rbu2n, tn >> 2, (tn & 3) << 7, w, lane);
        CP_COMMIT();

        // GEMM2 output chains (da: even kp4, db: odd kp4)
        float da[2][4], db[2][4];
        #pragma unroll
        for (int nt = 0; nt < 2; nt++) {
            float bz0 = b2s[nt*8 + 2*q], bz1 = b2s[nt*8 + 2*q + 1];
            da[nt][0] = bz0; da[nt][1] = bz1; da[nt][2] = bz0; da[nt][3] = bz1;
            db[nt][0] = 0.f; db[nt][1] = 0.f; db[nt][2] = 0.f; db[nt][3] = 0.f;
        }

        // ===== two hidden-halves: GEMM1 half -> fused pack + GEMM2 half =====
        #pragma unroll
        for (int hh2 = 0; hh2 < 2; hh2++) {
            float acc[8][4];
            #pragma unroll
            for (int j = 0; j < 8; j++) {
                int nt = hh2*8 + j;
                float bz0 = b1s[nt*8 + 2*q];
                float bz1 = b1s[nt*8 + 2*q + 1];
                acc[j][0] = bz0; acc[j][1] = bz1;
                acc[j][2] = bz0; acc[j][3] = bz1;
            }
            #pragma unroll
            for (int kc = 0; kc < 5; kc++) {
                const int o0 = foH[kc*2+0], o1 = foH[kc*2+1];
                const int r = R2 + gr;
                uint2 A0 = ruu[o0 + r];       // (hi, lo)
                uint2 A1 = ruu[o0 + r + 8];
                uint2 A2 = ruu[o1 + r];
                uint2 A3 = ruu[o1 + r + 8];
                uint4 bw[8];
                #pragma unroll
                for (int j = 0; j < 8; j++)
                    bw[j] = W1v[kc*512 + ((hh2*8 + j)*8 + gr)*4 + q];
                #pragma unroll
                for (int j = 0; j < 8; j++)
                    mma16(acc[j], A0.x, A1.x, A2.x, A3.x, bw[j].x, bw[j].y);
                #pragma unroll
                for (int j = 0; j < 8; j++)
                    mma16(acc[j], A0.y, A1.y, A2.y, A3.y, bw[j].x, bw[j].y);
                #pragma unroll
                for (int j = 0; j < 8; j++)
                    mma16(acc[j], A0.x, A1.x, A2.x, A3.x, bw[j].z, bw[j].w);
            }

            // fused epilogue + GEMM2 for this half's 4 k-chunks
            #pragma unroll
            for (int kp4 = 0; kp4 < 4; kp4++) {
                int kp = hh2*4 + kp4;
                uint32_t hhv[4], hlv[4];
                #pragma unroll
                for (int j = 0; j < 2; j++) {
                    float h0 = fmaxf(acc[2*kp4+j][0], 0.0f);
                    float h1 = fmaxf(acc[2*kp4+j][1], 0.0f);
                    float h2 = fmaxf(acc[2*kp4+j][2], 0.0f);
                    float h3 = fmaxf(acc[2*kp4+j][3], 0.0f);
                    uint32_t p0 = packbf(h1, h0);
                    uint32_t p1 = packbf(h3, h2);
                    hhv[2*j]   = p0;
                    hhv[2*j+1] = p1;
                    hlv[2*j]   = packbf(h1 - hi_f(p0), h0 - lo_f(p0));
                    hlv[2*j+1] = packbf(h3 - hi_f(p1), h2 - lo_f(p1));
                }
                uint4 wv0 = W2v[kp*64 + (0*8 + gr)*4 + q];
                uint4 wv1 = W2v[kp*64 + (1*8 + gr)*4 + q];
                float (*dd)[4] = (kp4 & 1) ? db : da;
                mma16(dd[0], hhv[0], hhv[1], hhv[2], hhv[3], wv0.x, wv0.y);
                mma16(dd[1], hhv[0], hhv[1], hhv[2], hhv[3], wv1.x, wv1.y);
                mma16(dd[0], hlv[0], hlv[1], hlv[2], hlv[3], wv0.x, wv0.y);
                mma16(dd[1], hlv[0], hlv[1], hlv[2], hlv[3], wv1.x, wv1.y);
                mma16(dd[0], hhv[0], hhv[1], hhv[2], hhv[3], wv0.z, wv0.w);
                mma16(dd[1], hhv[0], hhv[1], hhv[2], hhv[3], wv1.z, wv1.w);
            }
        }

        // ---- output: reconstruct center, add delta, re-split, one STG.64/pair ----
        {
            int px0  = R2 + gr;
            int pix0 = y*Wn + x0 + px0;
            #pragma unroll
            for (int nt = 0; nt < 2; nt++) {
                int c0  = nt*8 + 2*q;
                int pcb = c0 >> 1;
                int rowoff = (pcb*3 + 1)*RSU + 2;       // center row, px p at index 2+p
                #pragma unroll
                for (int h = 0; h < 2; h++) {
                    int px  = px0  + 8*h;
                    int pix = pix0 + 8*h;
                    uint2 cp = ruu[rowoff + px];
                    float ctr0 = lo_f(cp.x) + lo_f(cp.y);
                    float ctr1 = hi_f(cp.x) + hi_f(cp.y);
                    float d0 = da[nt][2*h]   + db[nt][2*h];
                    float d1 = da[nt][2*h+1] + db[nt][2*h+1];
                    float out0 = (c0 == 0) ? ctr0 : (ctr0 + d0);
                    float out1 = ctr1 + d1;
                    uint32_t ph = packbf(out1, out0);
                    dstP[pcb*HWn + pix] = make_uint2(ph, packbf(out1 - hi_f(ph), out0 - lo_f(ph)));
                    if (writeF32) {
                        dstF[c0*HWn + pix]     = out0;
                        dstF[(c0+1)*HWn + pix] = out1;
                    }
                }
            }
        }

        CP_WAIT0();
        __syncthreads();
        pb ^= 1;
    }
}

extern "C" void kernel_launch(void* const* d_in, const int* in_sizes, int n_in,
                              void* d_out, int out_size)
{
    const float* state = (const float*)d_in[0];
    const float* W1    = (const float*)d_in[1];
    const float* b1    = (const float*)d_in[2];
    const float* W2    = (const float*)d_in[3];
    const float* b2    = (const float*)d_in[4];
    float* out = (float*)d_out;

    cudaFuncSetAttribute(slime_step_mma,
                         cudaFuncAttributeMaxDynamicSharedMemorySize,
                         SMEM_WORDS * (int)sizeof(float));

    float* bufF;
    uint2 *PA, *PB;
    cudaGetSymbolAddress((void**)&bufF, g_bufF);
    cudaGetSymbolAddress((void**)&PA, g_PA);
    cudaGetSymbolAddress((void**)&PB, g_PB);

    w_setup<<<1, 256>>>(W1, W2);
    pack_state<<<(8*HWn)/256, 256>>>(state, PA);

    for (int s = 0; s < NSTEPS; s++) {
        const uint2* sP = (s & 1) ? PB : PA;
        uint2* dP = (s & 1) ? PA : PB;
        int last = (s == NSTEPS-1);
        slime_step_mma<<<GRIDX, NTHREADS, SMEM_WORDS*sizeof(float)>>>(
            sP, dP, last ? out : bufF, last, b1, b2);
    }
}